// round 3
// baseline (speedup 1.0000x reference)
#include <cuda_runtime.h>

#define NN 100000
#define NE 1600000
#define IND 75
#define H 64
#define HB 16
#define NB1 391        // ceil(NN/256) scan blocks

// Scratch (allocation-free rule: __device__ globals)
__device__ __align__(256) float g_hA[NN * H];
__device__ __align__(256) float g_hB[NN * H];
__device__ __align__(256) float g_P[NN * H];
__device__ __align__(256) float g_agg[NN * H];
// CSR build scratch
__device__ __align__(256) int   g_deg[NB1 * 256];
__device__ __align__(256) int   g_incl[NB1 * 256];
__device__ __align__(256) int   g_part[512];
__device__ __align__(256) int   g_off[NB1 * 256];
__device__ __align__(256) int   g_cursor[NB1 * 256];
__device__ __align__(256) int   g_srcs[NE];
__device__ __align__(256) float g_eats[(size_t)NE * HB];

// ---------------------------------------------------------------------------
// CSR build: histogram -> block scan -> partial scan -> offsets -> scatter
// ---------------------------------------------------------------------------
__global__ void hist_kernel(const int* __restrict__ edst, int* __restrict__ deg) {
    int e = blockIdx.x * blockDim.x + threadIdx.x;
    if (e < NE) atomicAdd(&deg[edst[e]], 1);
}

__global__ __launch_bounds__(256) void scan1_kernel(const int* __restrict__ deg,
                                                    int* __restrict__ incl,
                                                    int* __restrict__ part) {
    __shared__ int s[256];
    const int i = blockIdx.x * 256 + threadIdx.x;
    int v = (i < NN) ? deg[i] : 0;
    s[threadIdx.x] = v;
    __syncthreads();
#pragma unroll
    for (int o = 1; o < 256; o <<= 1) {
        int t = (threadIdx.x >= o) ? s[threadIdx.x - o] : 0;
        __syncthreads();
        s[threadIdx.x] += t;
        __syncthreads();
    }
    incl[i] = s[threadIdx.x];
    if (threadIdx.x == 255) part[blockIdx.x] = s[255];
}

__global__ __launch_bounds__(512) void scan2_kernel(int* __restrict__ part) {
    __shared__ int s[512];
    int v = (threadIdx.x < NB1) ? part[threadIdx.x] : 0;
    s[threadIdx.x] = v;
    __syncthreads();
#pragma unroll
    for (int o = 1; o < 512; o <<= 1) {
        int t = (threadIdx.x >= o) ? s[threadIdx.x - o] : 0;
        __syncthreads();
        s[threadIdx.x] += t;
        __syncthreads();
    }
    if (threadIdx.x < NB1) part[threadIdx.x] = s[threadIdx.x] - v;  // exclusive
}

__global__ __launch_bounds__(256) void scan3_kernel(const int* __restrict__ deg,
                                                    const int* __restrict__ incl,
                                                    const int* __restrict__ part,
                                                    int* __restrict__ off,
                                                    int* __restrict__ cursor) {
    const int i = blockIdx.x * 256 + threadIdx.x;
    if (i < NN) {
        int o = incl[i] - deg[i] + part[blockIdx.x];
        off[i] = o;
        cursor[i] = o;
    }
}

__global__ void scatter_kernel(const int* __restrict__ esrc,
                               const int* __restrict__ edst,
                               const float* __restrict__ eattr,
                               int* __restrict__ cursor,
                               int* __restrict__ srcs,
                               float* __restrict__ eats) {
    int e = blockIdx.x * blockDim.x + threadIdx.x;
    if (e >= NE) return;
    int pos = atomicAdd(&cursor[edst[e]], 1);
    srcs[pos] = esrc[e];
    const float4* a = (const float4*)(eattr + (size_t)e * HB);
    float4* b = (float4*)(eats + (size_t)pos * HB);
    b[0] = a[0]; b[1] = a[1]; b[2] = a[2]; b[3] = a[3];
}

// ---------------------------------------------------------------------------
// proj: out = x @ W(75x64) + b     (run once)
// ---------------------------------------------------------------------------
__global__ __launch_bounds__(256) void proj_kernel(const float* __restrict__ x,
                                                   const float* __restrict__ w,
                                                   const float* __restrict__ b,
                                                   float* __restrict__ out) {
    __shared__ float sW[IND][H];
    __shared__ float sA[32][IND + 1];
    for (int i = threadIdx.x; i < IND * H; i += 256) sW[i / H][i % H] = w[i];

    const int lane = threadIdx.x & 31, wid = threadIdx.x >> 5;
    const int nl = lane & 3, cg = lane >> 2;
    const int myn = wid * 4 + nl;
    const float4 bb0 = *(const float4*)&b[cg * 8];
    const float4 bb1 = *(const float4*)&b[cg * 8 + 4];

    for (int tile = blockIdx.x; tile < NN / 32; tile += gridDim.x) {
        const int base = tile * 32;
        __syncthreads();
        for (int i = threadIdx.x; i < 32 * IND; i += 256)
            sA[i / IND][i % IND] = x[(size_t)base * IND + i];
        __syncthreads();

        float acc[8] = {bb0.x, bb0.y, bb0.z, bb0.w, bb1.x, bb1.y, bb1.z, bb1.w};
#pragma unroll 5
        for (int k = 0; k < IND; k++) {
            const float a = sA[myn][k];
            const float4 w0 = *(const float4*)&sW[k][cg * 8];
            const float4 w1 = *(const float4*)&sW[k][cg * 8 + 4];
            acc[0] += a * w0.x; acc[1] += a * w0.y; acc[2] += a * w0.z; acc[3] += a * w0.w;
            acc[4] += a * w1.x; acc[5] += a * w1.y; acc[6] += a * w1.z; acc[7] += a * w1.w;
        }
        const size_t o = (size_t)(base + myn) * H + cg * 8;
        *(float4*)&out[o]     = make_float4(acc[0], acc[1], acc[2], acc[3]);
        *(float4*)&out[o + 4] = make_float4(acc[4], acc[5], acc[6], acc[7]);
    }
}

// ---------------------------------------------------------------------------
// pk: P = h @ W2h(64x64) + b2
// ---------------------------------------------------------------------------
__global__ __launch_bounds__(256) void pk_kernel(const float* __restrict__ h,
                                                 const float* __restrict__ w,
                                                 const float* __restrict__ b,
                                                 float* __restrict__ P) {
    __shared__ float sW[H][H];
    __shared__ float sA[32][H + 1];
    for (int i = threadIdx.x; i < H * H; i += 256) sW[i >> 6][i & 63] = w[i];

    const int lane = threadIdx.x & 31, wid = threadIdx.x >> 5;
    const int nl = lane & 3, cg = lane >> 2;
    const int myn = wid * 4 + nl;
    const float4 bb0 = *(const float4*)&b[cg * 8];
    const float4 bb1 = *(const float4*)&b[cg * 8 + 4];

    for (int tile = blockIdx.x; tile < NN / 32; tile += gridDim.x) {
        const int base = tile * 32;
        __syncthreads();
        for (int i = threadIdx.x; i < 32 * H; i += 256)
            sA[i >> 6][i & 63] = h[(size_t)base * H + i];
        __syncthreads();

        float acc[8] = {bb0.x, bb0.y, bb0.z, bb0.w, bb1.x, bb1.y, bb1.z, bb1.w};
#pragma unroll 8
        for (int k = 0; k < H; k++) {
            const float a = sA[myn][k];
            const float4 w0 = *(const float4*)&sW[k][cg * 8];
            const float4 w1 = *(const float4*)&sW[k][cg * 8 + 4];
            acc[0] += a * w0.x; acc[1] += a * w0.y; acc[2] += a * w0.z; acc[3] += a * w0.w;
            acc[4] += a * w1.x; acc[5] += a * w1.y; acc[6] += a * w1.z; acc[7] += a * w1.w;
        }
        const size_t o = (size_t)(base + myn) * H + cg * 8;
        *(float4*)&P[o]     = make_float4(acc[0], acc[1], acc[2], acc[3]);
        *(float4*)&P[o + 4] = make_float4(acc[4], acc[5], acc[6], acc[7]);
    }
}

// ---------------------------------------------------------------------------
// gather: for node n: agg[n] = sum over incoming edges of
//         leakyrelu(P[src] + eattr_csr @ W2e).  Warp per node, 2 edges/iter
//         (one per half-warp), no atomics.
// ---------------------------------------------------------------------------
__global__ __launch_bounds__(256) void gather_kernel(const int* __restrict__ off,
                                                     const int* __restrict__ deg,
                                                     const int* __restrict__ srcs,
                                                     const float* __restrict__ eats,
                                                     const float* __restrict__ w2e,
                                                     const float* __restrict__ P,
                                                     float* __restrict__ agg) {
    __shared__ float sW[HB][H];  // 4096 B
    for (int i = threadIdx.x; i < HB * H; i += 256) sW[i >> 6][i & 63] = w2e[i];
    __syncthreads();

    const int lane = threadIdx.x & 31, wid = threadIdx.x >> 5;
    const int half = lane >> 4, hl = lane & 15;

    for (int n = blockIdx.x * 8 + wid; n < NN; n += gridDim.x * 8) {
        const int start = off[n];
        const int d = deg[n];
        const int iters = (d + 1) >> 1;
        float4 acc = make_float4(0.f, 0.f, 0.f, 0.f);

        for (int j = 0; j < iters; j++) {
            const int r = 2 * j + half;
            const bool act = r < d;
            int pos = start + r;
            if (pos > NE - 1) pos = NE - 1;
            const int src = srcs[pos];
            const float ev = eats[(size_t)pos * HB + hl];

            float4 m = *(const float4*)(P + (size_t)src * H + hl * 4);
#pragma unroll
            for (int k = 0; k < HB; k++) {
                const float ek = __shfl_sync(0xffffffffu, ev, k, 16);
                const float4 wv = *(const float4*)&sW[k][hl * 4];
                m.x += ek * wv.x; m.y += ek * wv.y;
                m.z += ek * wv.z; m.w += ek * wv.w;
            }
            m.x = fmaxf(m.x, 0.1f * m.x);
            m.y = fmaxf(m.y, 0.1f * m.y);
            m.z = fmaxf(m.z, 0.1f * m.z);
            m.w = fmaxf(m.w, 0.1f * m.w);
            if (act) {
                acc.x += m.x; acc.y += m.y; acc.z += m.z; acc.w += m.w;
            }
        }
        acc.x += __shfl_down_sync(0xffffffffu, acc.x, 16);
        acc.y += __shfl_down_sync(0xffffffffu, acc.y, 16);
        acc.z += __shfl_down_sync(0xffffffffu, acc.z, 16);
        acc.w += __shfl_down_sync(0xffffffffu, acc.w, 16);
        if (half == 0)
            *(float4*)(agg + (size_t)n * H + hl * 4) = acc;
    }
}

// ---------------------------------------------------------------------------
// upd: out = concat(h, agg) @ W1(128x64) + b1
// ---------------------------------------------------------------------------
__global__ __launch_bounds__(256) void upd_kernel(const float* __restrict__ h,
                                                  const float* __restrict__ agg,
                                                  const float* __restrict__ w,
                                                  const float* __restrict__ b,
                                                  float* __restrict__ out) {
    __shared__ float sW[2 * H][H];   // 32768 B
    __shared__ float sA[32][2 * H];  // 16384 B, XOR-swizzled by (row&3)<<3
    for (int i = threadIdx.x; i < 2 * H * H; i += 256) sW[i >> 6][i & 63] = w[i];

    const int lane = threadIdx.x & 31, wid = threadIdx.x >> 5;
    const int nl = lane & 3, cg = lane >> 2;
    const int myn = wid * 4 + nl;
    const int swz = nl << 3;
    const float4 bb0 = *(const float4*)&b[cg * 8];
    const float4 bb1 = *(const float4*)&b[cg * 8 + 4];

    for (int tile = blockIdx.x; tile < NN / 32; tile += gridDim.x) {
        const int base = tile * 32;
        __syncthreads();
        for (int i = threadIdx.x; i < 32 * H; i += 256) {
            const int r = i >> 6, c = i & 63;
            const int s = (r & 3) << 3;
            sA[r][c ^ s]        = h[(size_t)base * H + i];
            sA[r][(c + 64) ^ s] = agg[(size_t)base * H + i];
        }
        __syncthreads();

        float acc[8] = {bb0.x, bb0.y, bb0.z, bb0.w, bb1.x, bb1.y, bb1.z, bb1.w};
#pragma unroll 8
        for (int k = 0; k < 2 * H; k++) {
            const float a = sA[myn][k ^ swz];
            const float4 w0 = *(const float4*)&sW[k][cg * 8];
            const float4 w1 = *(const float4*)&sW[k][cg * 8 + 4];
            acc[0] += a * w0.x; acc[1] += a * w0.y; acc[2] += a * w0.z; acc[3] += a * w0.w;
            acc[4] += a * w1.x; acc[5] += a * w1.y; acc[6] += a * w1.z; acc[7] += a * w1.w;
        }
        const size_t o = (size_t)(base + myn) * H + cg * 8;
        *(float4*)&out[o]     = make_float4(acc[0], acc[1], acc[2], acc[3]);
        *(float4*)&out[o + 4] = make_float4(acc[4], acc[5], acc[6], acc[7]);
    }
}

// ---------------------------------------------------------------------------
extern "C" void kernel_launch(void* const* d_in, const int* in_sizes, int n_in,
                              void* d_out, int out_size) {
    const float* x      = (const float*)d_in[0];   // [100000, 75]
    const int*   eidx   = (const int*)d_in[1];     // [2, 1600000] (int64 -> int32)
    const float* eattr  = (const float*)d_in[2];   // [1600000, 16]
    const float* proj_w = (const float*)d_in[3];
    const float* proj_b = (const float*)d_in[4];
    const float* u2w    = (const float*)d_in[5];   // [3, 80, 64]
    const float* u2b    = (const float*)d_in[6];
    const float* u1w    = (const float*)d_in[7];   // [3, 128, 64]
    const float* u1b    = (const float*)d_in[8];
    float*       out    = (float*)d_out;           // [100000, 64]

    float *hA, *hB, *P, *agg, *eats;
    int *deg, *incl, *part, *off, *cursor, *srcs;
    cudaGetSymbolAddress((void**)&hA, g_hA);
    cudaGetSymbolAddress((void**)&hB, g_hB);
    cudaGetSymbolAddress((void**)&P, g_P);
    cudaGetSymbolAddress((void**)&agg, g_agg);
    cudaGetSymbolAddress((void**)&deg, g_deg);
    cudaGetSymbolAddress((void**)&incl, g_incl);
    cudaGetSymbolAddress((void**)&part, g_part);
    cudaGetSymbolAddress((void**)&off, g_off);
    cudaGetSymbolAddress((void**)&cursor, g_cursor);
    cudaGetSymbolAddress((void**)&srcs, g_srcs);
    cudaGetSymbolAddress((void**)&eats, g_eats);

    const int* esrc = eidx;
    const int* edst = eidx + NE;

    // CSR build (once per launch; reused by all 3 layers)
    cudaMemsetAsync(deg, 0, NB1 * 256 * sizeof(int));
    hist_kernel<<<(NE + 255) / 256, 256>>>(edst, deg);
    scan1_kernel<<<NB1, 256>>>(deg, incl, part);
    scan2_kernel<<<1, 512>>>(part);
    scan3_kernel<<<NB1, 256>>>(deg, incl, part, off, cursor);
    scatter_kernel<<<(NE + 255) / 256, 256>>>(esrc, edst, eattr, cursor, srcs, eats);

    proj_kernel<<<592, 256>>>(x, proj_w, proj_b, hA);

    for (int l = 0; l < 3; l++) {
        const float* hin = (l == 1) ? hB : hA;          // l0:A, l1:B, l2:A
        float* hout = (l == 0) ? hB : ((l == 1) ? hA : out);
        const float* w2 = u2w + (size_t)l * 80 * 64;     // rows 0..63 = W2h, 64..79 = W2e
        pk_kernel<<<592, 256>>>(hin, w2, u2b + l * 64, P);
        gather_kernel<<<1184, 256>>>(off, deg, srcs, eats, w2 + 64 * 64, P, agg);
        upd_kernel<<<592, 256>>>(hin, agg, u1w + (size_t)l * 128 * 64, u1b + l * 64, hout);
    }
}